// round 3
// baseline (speedup 1.0000x reference)
#include <cuda_runtime.h>
#include <math.h>

// ---------------- problem constants ----------------
#define NB      32
#define FH      11
#define FW      20
#define NEDGE   42
#define NANG    17
#define NPRED   77
#define NPROP   714
#define NOFF    72
#define KBACK   512
#define KCONV   1024
#define NREG    1241
#define NCLS    34
#define NPAD    1280        // NREG + NCLS padded to 128 multiple
#define MROWS   1344        // NB * NEDGE
#define NWORDS  23
#define NSTRIPSF 71.0f
#define NMS_T   15.0f

// ---------------- scratch ----------------
__device__ float    g_featET[KBACK * MROWS];
__device__ float    g_convT [KCONV * MROWS];
__device__ float    g_rc    [MROWS * NPAD];          // fused reg|cls output
__device__ float    g_Wc    [NPAD * KCONV];          // packed W_reg|W_cls
__device__ float    g_bc    [NPAD];
__device__ int      g_order [NB * NPROP];
__device__ float    g_sstart[NB * NPROP];
__device__ float    g_send  [NB * NPROP];
__device__ float    g_sxs   [NB * NPROP * NOFF];
__device__ unsigned g_sup   [NB * NPROP * NWORDS];

// ---------------- pack combined weights (reg | cls | zero pad) ----------------
__global__ void k_packW(const float* __restrict__ Wr, const float* __restrict__ br,
                        const float* __restrict__ Wc, const float* __restrict__ bc) {
    int i = blockIdx.x * blockDim.x + threadIdx.x;      // float4 index
    if (i < NPAD * (KCONV / 4)) {
        int row = i >> 8;                                // /256
        int c4  = i & 255;
        float4 v = make_float4(0.f, 0.f, 0.f, 0.f);
        if (row < NREG)      v = *reinterpret_cast<const float4*>(&Wr[(size_t)row * KCONV + c4 * 4]);
        else if (row < NREG + NCLS)
                             v = *reinterpret_cast<const float4*>(&Wc[(size_t)(row - NREG) * KCONV + c4 * 4]);
        reinterpret_cast<float4*>(g_Wc)[i] = v;
    }
    if (i < NPAD) {
        float v = 0.f;
        if (i < NREG)            v = br[i];
        else if (i < NREG + NCLS) v = bc[i - NREG];
        g_bc[i] = v;
    }
}

// ---------------- gather edge features into A^T layout ----------------
__global__ void k_gather(const float* __restrict__ feat) {
    int x = blockIdx.x * blockDim.x + threadIdx.x;
    if (x >= KBACK * MROWS) return;
    int m = x % MROWS;
    int c = x / MROWS;
    int b = m / NEDGE, e = m % NEDGE;
    int h, w;
    if (e < FH)        { h = e;      w = 0;        }
    else if (e < 2*FH) { h = e - FH; w = FW - 1;   }
    else               { h = FH - 1; w = e - 2*FH; }
    g_featET[x] = feat[((size_t)(b * KBACK + c) * FH + h) * FW + w];
}

// ---------------- fp32 GEMM, fma.rn.f32x2, 32x128 tile, db smem ----------------
// C[m][n] = sum_k AT[k][m] * W[n][k] + bias[n];  K%16==0, N%128==0, M%32==0
template<int TRANS_OUT>
__global__ __launch_bounds__(256) void k_gemm(
    const float* __restrict__ AT, const float* __restrict__ W,
    const float* __restrict__ bias, float* __restrict__ C,
    int K, int N)
{
    __shared__ unsigned long long As2[2][16][32];   // (a,a) pairs, 4KB each
    __shared__ float              Bs [2][16][132];  // +4 pad, 8.25KB each
    const int m0 = blockIdx.y * 32;
    const int n0 = blockIdx.x * 128;
    const int t  = threadIdx.x;
    const int tx = t & 15, ty = t >> 4;

    // global-load indices (A: one float2/thread, B: two float4/thread)
    const int kkA = t >> 4, mpA = t & 15;
    const int nB0 = t >> 2,         kwB0 = t & 3;
    const int nB1 = (t + 256) >> 2, kwB1 = (t + 256) & 3;

    const int ntiles = K >> 4;
    float2 ra;  float4 rb0, rb1;

    auto load_tile = [&](int k0) {
        ra  = *reinterpret_cast<const float2*>(&AT[(size_t)(k0 + kkA) * MROWS + m0 + mpA * 2]);
        rb0 = *reinterpret_cast<const float4*>(&W[(size_t)(n0 + nB0) * K + k0 + kwB0 * 4]);
        rb1 = *reinterpret_cast<const float4*>(&W[(size_t)(n0 + nB1) * K + k0 + kwB1 * 4]);
    };
    auto store_tile = [&](int buf) {
        unsigned long long px, py;
        asm("mov.b64 %0, {%1, %1};" : "=l"(px) : "f"(ra.x));
        asm("mov.b64 %0, {%1, %1};" : "=l"(py) : "f"(ra.y));
        As2[buf][kkA][mpA * 2]     = px;
        As2[buf][kkA][mpA * 2 + 1] = py;
        Bs[buf][kwB0 * 4 + 0][nB0] = rb0.x;
        Bs[buf][kwB0 * 4 + 1][nB0] = rb0.y;
        Bs[buf][kwB0 * 4 + 2][nB0] = rb0.z;
        Bs[buf][kwB0 * 4 + 3][nB0] = rb0.w;
        Bs[buf][kwB1 * 4 + 0][nB1] = rb1.x;
        Bs[buf][kwB1 * 4 + 1][nB1] = rb1.y;
        Bs[buf][kwB1 * 4 + 2][nB1] = rb1.z;
        Bs[buf][kwB1 * 4 + 3][nB1] = rb1.w;
    };

    unsigned long long acc[2][4];
#pragma unroll
    for (int r = 0; r < 2; r++)
#pragma unroll
        for (int c = 0; c < 4; c++) acc[r][c] = 0ull;

    load_tile(0);
    store_tile(0);
    if (ntiles > 1) load_tile(16);   // regs now hold tile 1
    __syncthreads();

    for (int i = 0; i < ntiles; i++) {
        int buf = i & 1;
        if (i + 1 < ntiles) store_tile((i + 1) & 1);      // safe: that buf last read at i-1
        if (i + 2 < ntiles) load_tile((i + 2) << 4);      // latency hidden by compute
#pragma unroll
        for (int kk = 0; kk < 16; kk++) {
            ulonglong2 a   = *reinterpret_cast<const ulonglong2*>(&As2[buf][kk][ty * 2]);
            ulonglong2 b01 = *reinterpret_cast<const ulonglong2*>(&Bs[buf][kk][tx * 8]);
            ulonglong2 b23 = *reinterpret_cast<const ulonglong2*>(&Bs[buf][kk][tx * 8 + 4]);
            asm("fma.rn.f32x2 %0, %1, %2, %0;" : "+l"(acc[0][0]) : "l"(a.x), "l"(b01.x));
            asm("fma.rn.f32x2 %0, %1, %2, %0;" : "+l"(acc[0][1]) : "l"(a.x), "l"(b01.y));
            asm("fma.rn.f32x2 %0, %1, %2, %0;" : "+l"(acc[0][2]) : "l"(a.x), "l"(b23.x));
            asm("fma.rn.f32x2 %0, %1, %2, %0;" : "+l"(acc[0][3]) : "l"(a.x), "l"(b23.y));
            asm("fma.rn.f32x2 %0, %1, %2, %0;" : "+l"(acc[1][0]) : "l"(a.y), "l"(b01.x));
            asm("fma.rn.f32x2 %0, %1, %2, %0;" : "+l"(acc[1][1]) : "l"(a.y), "l"(b01.y));
            asm("fma.rn.f32x2 %0, %1, %2, %0;" : "+l"(acc[1][2]) : "l"(a.y), "l"(b23.x));
            asm("fma.rn.f32x2 %0, %1, %2, %0;" : "+l"(acc[1][3]) : "l"(a.y), "l"(b23.y));
        }
        __syncthreads();
    }

    // epilogue
    float bv[8];
#pragma unroll
    for (int i = 0; i < 8; i++) bv[i] = bias[n0 + tx * 8 + i];
#pragma unroll
    for (int r = 0; r < 2; r++) {
        int m = m0 + ty * 2 + r;
        float v[8];
#pragma unroll
        for (int c = 0; c < 4; c++) {
            float lo, hi;
            asm("mov.b64 {%0, %1}, %2;" : "=f"(lo), "=f"(hi) : "l"(acc[r][c]));
            v[c * 2]     = lo + bv[c * 2];
            v[c * 2 + 1] = hi + bv[c * 2 + 1];
        }
        if (TRANS_OUT) {
#pragma unroll
            for (int i = 0; i < 8; i++)
                C[(size_t)(n0 + tx * 8 + i) * MROWS + m] = v[i];
        } else {
            *reinterpret_cast<float4*>(&C[(size_t)m * N + n0 + tx * 8])
                = make_float4(v[0], v[1], v[2], v[3]);
            *reinterpret_cast<float4*>(&C[(size_t)m * N + n0 + tx * 8 + 4])
                = make_float4(v[4], v[5], v[6], v[7]);
        }
    }
}

// ---------------- assemble proposals + scores ----------------
__global__ void k_assemble(const float* __restrict__ anchd, float* __restrict__ out) {
    int row = blockIdx.x;            // b*42+e
    int b = row / NEDGE, e = row % NEDGE;
    float* prop   = out + (size_t)b * NPROP * NPRED;
    float* scores = out + (size_t)NB * NPROP * NPRED + (size_t)NB * NPROP + (size_t)b * NPROP;
    const float* rc = g_rc + (size_t)row * NPAD;
    for (int l = threadIdx.x; l < NANG * NPRED; l += blockDim.x) {
        int a = l / NPRED, q = l % NPRED;
        int p = e * NANG + a;
        float v;
        if (q < 2)      v = rc[NREG + a * 2 + q];
        else if (q < 4) v = anchd[(size_t)p * NPRED + q];
        else            v = anchd[(size_t)p * NPRED + q] + rc[a * 73 + (q - 4)];
        prop[(size_t)p * NPRED + q] = v;
    }
    if (threadIdx.x < NANG) {
        int a = threadIdx.x;
        int p = e * NANG + a;
        float l0 = rc[NREG + a * 2];
        float l1 = rc[NREG + a * 2 + 1];
        scores[p] = 1.0f / (1.0f + expf(l0 - l1));
    }
}

// ---------------- NMS: stable descending argsort + sorted gather ----------------
__global__ void k_sort(const float* __restrict__ out) {
    int b = blockIdx.x;
    __shared__ float s[NPROP];
    const float* scores = out + (size_t)NB * NPROP * NPRED + (size_t)NB * NPROP + (size_t)b * NPROP;
    const float* prop   = out + (size_t)b * NPROP * NPRED;
    for (int i = threadIdx.x; i < NPROP; i += blockDim.x) s[i] = scores[i];
    __syncthreads();
    for (int i = threadIdx.x; i < NPROP; i += blockDim.x) {
        float si = s[i];
        int r = 0;
        for (int j = 0; j < NPROP; j++) {
            float sj = s[j];
            r += (sj > si) || (sj == si && j < i);
        }
        int base = b * NPROP + r;
        g_order[base] = i;
        float p2 = prop[(size_t)i * NPRED + 2];
        float p4 = prop[(size_t)i * NPRED + 4];
        float st = fminf(fmaxf(rintf(p2 * NSTRIPSF), 0.0f), NSTRIPSF);
        float en = fminf(fmaxf(st + p4 - 1.0f, 0.0f), NSTRIPSF);
        g_sstart[base] = st;
        g_send[base]   = en;
        float* dst = g_sxs + (size_t)base * NOFF;
        const float* src = prop + (size_t)i * NPRED + 5;
        for (int k = 0; k < NOFF; k++) dst[k] = src[k];
    }
}

// ---------------- NMS: pairwise suppression bitmatrix ----------------
__global__ void k_pairs() {
    int b    = blockIdx.y;
    int warp = threadIdx.x >> 5;
    int lane = threadIdx.x & 31;
    int i    = blockIdx.x * 8 + warp;
    if (i >= NPROP) return;
    int base = b * NPROP;
    float si = g_sstart[base + i], ei = g_send[base + i];
    const float* xi = g_sxs + (size_t)(base + i) * NOFF;
    for (int jw = 0; jw < NWORDS; jw++) {
        int j = jw * 32 + lane;
        bool sup = false;
        if (j < NPROP) {
            float s  = fmaxf(si, g_sstart[base + j]);
            float e  = fminf(ei, g_send[base + j]);
            float cnt = e - s + 1.0f;
            if (cnt > 0.0f) {
                const float* xj = g_sxs + (size_t)(base + j) * NOFF;
                int k0 = (int)s;
                int k1 = (int)floorf(e);
                float sum = 0.0f;
                for (int k = k0; k <= k1; k++) sum += fabsf(xi[k] - xj[k]);
                sup = (sum / fmaxf(cnt, 1.0f)) < NMS_T;
            }
        }
        unsigned m = __ballot_sync(0xFFFFFFFFu, sup);
        if (lane == 0) g_sup[(size_t)(base + i) * NWORDS + jw] = m;
    }
}

// ---------------- NMS: sequential scan (one warp per batch) ----------------
__global__ void k_scan(float* __restrict__ out) {
    int b    = blockIdx.x;
    int lane = threadIdx.x;
    float* keep = out + (size_t)NB * NPROP * NPRED + (size_t)b * NPROP;
    int base = b * NPROP;
    unsigned my = 0;
    unsigned row_next = (lane < NWORDS) ? g_sup[(size_t)base * NWORDS + lane] : 0u;
    for (int i = 0; i < NPROP; i++) {
        unsigned row = row_next;
        if (i + 1 < NPROP && lane < NWORDS)
            row_next = g_sup[(size_t)(base + i + 1) * NWORDS + lane];
        int wi = i >> 5, bit = i & 31;
        unsigned wsup = __shfl_sync(0xFFFFFFFFu, my, wi);
        bool kept = ((wsup >> bit) & 1u) == 0u;
        if (kept) {
            unsigned m;
            if (lane > wi)       m = 0xFFFFFFFFu;
            else if (lane == wi) m = (bit == 31) ? 0u : (0xFFFFFFFFu << (bit + 1));
            else                 m = 0u;
            my |= row & m;
        }
        if (lane == 0) keep[g_order[base + i]] = kept ? 1.0f : 0.0f;
    }
}

// ---------------- launcher ----------------
extern "C" void kernel_launch(void* const* d_in, const int* in_sizes, int n_in,
                              void* d_out, int out_size) {
    const float* feat   = (const float*)d_in[0];
    const float* W_conv = (const float*)d_in[1];
    const float* b_conv = (const float*)d_in[2];
    const float* W_cls  = (const float*)d_in[3];
    const float* b_cls  = (const float*)d_in[4];
    const float* W_reg  = (const float*)d_in[5];
    const float* b_reg  = (const float*)d_in[6];
    const float* anchd  = (const float*)d_in[8];
    float* out = (float*)d_out;

    void *p_featET, *p_convT, *p_rc, *p_Wc, *p_bc;
    cudaGetSymbolAddress(&p_featET, g_featET);
    cudaGetSymbolAddress(&p_convT,  g_convT);
    cudaGetSymbolAddress(&p_rc,     g_rc);
    cudaGetSymbolAddress(&p_Wc,     g_Wc);
    cudaGetSymbolAddress(&p_bc,     g_bc);

    k_packW<<<(NPAD * (KCONV / 4) + 255) / 256, 256>>>(W_reg, b_reg, W_cls, b_cls);
    k_gather<<<(KBACK * MROWS + 255) / 256, 256>>>(feat);
    k_gemm<1><<<dim3(KCONV / 128, MROWS / 32), 256>>>(
        (const float*)p_featET, W_conv, b_conv, (float*)p_convT, KBACK, KCONV);
    k_gemm<0><<<dim3(NPAD / 128, MROWS / 32), 256>>>(
        (const float*)p_convT, (const float*)p_Wc, (const float*)p_bc,
        (float*)p_rc, KCONV, NPAD);
    k_assemble<<<MROWS, 256>>>(anchd, out);
    k_sort<<<NB, 256>>>(out);
    k_pairs<<<dim3((NPROP + 7) / 8, NB), 256>>>();
    k_scan<<<NB, 32>>>(out);
}

// round 4
// speedup vs baseline: 1.6266x; 1.6266x over previous
#include <cuda_runtime.h>
#include <math.h>

// ---------------- problem constants ----------------
#define NB      32
#define FH      11
#define FW      20
#define NEDGE   42
#define NANG    17
#define NPRED   77
#define NPROP   714
#define NOFF    72
#define KBACK   512
#define KCONV   1024
#define NREG    1241
#define NCLS    34
#define NPAD    1280        // NREG + NCLS padded to 128 multiple
#define MROWS   1344        // NB * NEDGE
#define NWORDS  23
#define NSTRIPSF 71.0f
#define NMS_T   15.0f
#define NCHUNK  128
#define NCHUNKS 6           // ceil(714/128)

// ---------------- scratch ----------------
__device__ float    g_featE [MROWS * KBACK];         // [m][c] row-major
__device__ float    g_conv  [MROWS * KCONV];         // [m][n] row-major
__device__ float    g_rc    [MROWS * NPAD];          // fused reg|cls output
__device__ float    g_Wc    [NPAD * KCONV];          // packed W_reg|W_cls
__device__ float    g_bc    [NPAD];
__device__ int      g_order [NB * NPROP];
__device__ float    g_sstart[NB * NPROP];
__device__ float    g_send  [NB * NPROP];
__device__ float    g_sxs   [NB * NPROP * NOFF];
__device__ unsigned g_sup   [NB * NPROP * NWORDS];

// ---------------- pack combined weights (reg | cls | zero pad) ----------------
__global__ void k_packW(const float* __restrict__ Wr, const float* __restrict__ br,
                        const float* __restrict__ Wc, const float* __restrict__ bc) {
    int i = blockIdx.x * blockDim.x + threadIdx.x;      // float4 index
    if (i < NPAD * (KCONV / 4)) {
        int row = i >> 8;
        int c4  = i & 255;
        float4 v = make_float4(0.f, 0.f, 0.f, 0.f);
        if (row < NREG)      v = *reinterpret_cast<const float4*>(&Wr[(size_t)row * KCONV + c4 * 4]);
        else if (row < NREG + NCLS)
                             v = *reinterpret_cast<const float4*>(&Wc[(size_t)(row - NREG) * KCONV + c4 * 4]);
        reinterpret_cast<float4*>(g_Wc)[i] = v;
    }
    if (i < NPAD) {
        float v = 0.f;
        if (i < NREG)             v = br[i];
        else if (i < NREG + NCLS) v = bc[i - NREG];
        g_bc[i] = v;
    }
}

// ---------------- gather edge features, row-major [m][c] ----------------
__global__ void k_gather(const float* __restrict__ feat) {
    int x = blockIdx.x * blockDim.x + threadIdx.x;
    if (x >= KBACK * MROWS) return;
    int c = x & (KBACK - 1);
    int m = x >> 9;
    int b = m / NEDGE, e = m % NEDGE;
    int h, w;
    if (e < FH)        { h = e;      w = 0;        }
    else if (e < 2*FH) { h = e - FH; w = FW - 1;   }
    else               { h = FH - 1; w = e - 2*FH; }
    g_featE[x] = feat[((size_t)(b * KBACK + c) * FH + h) * FW + w];
}

// ---------------- fp32 GEMM, fma.rn.f32x2, 64Mx128N tile, 8x8 microtile ----------------
// C[m][n] = sum_k A[m][k] * W[n][k] + bias[n];  row-major everything.
// 128 threads; K % 16 == 0, N % 128 == 0, M % 64 == 0.
__global__ __launch_bounds__(128) void k_gemm(
    const float* __restrict__ A, const float* __restrict__ W,
    const float* __restrict__ bias, float* __restrict__ C,
    int K, int N)
{
    __shared__ __align__(16) unsigned long long As2[2][16][66];   // [kk][m] dup (a,a) pairs
    __shared__ __align__(16) float              Bsf[2][16][4][34];// [kk][j][tx*2+e]
    const int m0 = blockIdx.y * 64;
    const int n0 = blockIdx.x * 128;
    const int t  = threadIdx.x;
    const int tx = t & 15, ty = t >> 4;

    const int ntiles = K >> 4;
    float4 ra[2], rb[4];

    auto load_tile = [&](int k0) {
#pragma unroll
        for (int i = 0; i < 2; i++) {
            int idx = t + i * 128;
            int m = idx >> 2, kq = idx & 3;
            ra[i] = *reinterpret_cast<const float4*>(&A[(size_t)(m0 + m) * K + k0 + kq * 4]);
        }
#pragma unroll
        for (int i = 0; i < 4; i++) {
            int idx = t + i * 128;
            int n = idx >> 2, kw = idx & 3;
            rb[i] = *reinterpret_cast<const float4*>(&W[(size_t)(n0 + n) * K + k0 + kw * 4]);
        }
    };
    auto store_tile = [&](int buf) {
#pragma unroll
        for (int i = 0; i < 2; i++) {
            int idx = t + i * 128;
            int m = idx >> 2, kq = idx & 3;
            float v[4] = {ra[i].x, ra[i].y, ra[i].z, ra[i].w};
#pragma unroll
            for (int j = 0; j < 4; j++) {
                unsigned long long p;
                asm("mov.b64 %0, {%1, %1};" : "=l"(p) : "f"(v[j]));
                As2[buf][kq * 4 + j][m] = p;
            }
        }
#pragma unroll
        for (int i = 0; i < 4; i++) {
            int idx = t + i * 128;
            int n = idx >> 2, kw = idx & 3;
            int jj = (n >> 1) & 3, ee = (n >> 3) * 2 + (n & 1);
            float v[4] = {rb[i].x, rb[i].y, rb[i].z, rb[i].w};
#pragma unroll
            for (int q = 0; q < 4; q++)
                Bsf[buf][kw * 4 + q][jj][ee] = v[q];
        }
    };

    unsigned long long acc[8][4];
#pragma unroll
    for (int r = 0; r < 8; r++)
#pragma unroll
        for (int c = 0; c < 4; c++) acc[r][c] = 0ull;

    load_tile(0);
    store_tile(0);
    if (ntiles > 1) load_tile(16);
    __syncthreads();

    for (int i = 0; i < ntiles; i++) {
        int buf = i & 1;
        if (i + 1 < ntiles) store_tile((i + 1) & 1);
        if (i + 2 < ntiles) load_tile((i + 2) << 4);
#pragma unroll
        for (int kk = 0; kk < 16; kk++) {
            ulonglong2 a01 = *reinterpret_cast<const ulonglong2*>(&As2[buf][kk][ty * 8 + 0]);
            ulonglong2 a23 = *reinterpret_cast<const ulonglong2*>(&As2[buf][kk][ty * 8 + 2]);
            ulonglong2 a45 = *reinterpret_cast<const ulonglong2*>(&As2[buf][kk][ty * 8 + 4]);
            ulonglong2 a67 = *reinterpret_cast<const ulonglong2*>(&As2[buf][kk][ty * 8 + 6]);
            unsigned long long b[4];
#pragma unroll
            for (int j = 0; j < 4; j++)
                b[j] = *reinterpret_cast<const unsigned long long*>(&Bsf[buf][kk][j][tx * 2]);
            unsigned long long av[8] = {a01.x, a01.y, a23.x, a23.y, a45.x, a45.y, a67.x, a67.y};
#pragma unroll
            for (int r = 0; r < 8; r++) {
#pragma unroll
                for (int j = 0; j < 4; j++)
                    asm("fma.rn.f32x2 %0, %1, %2, %0;" : "+l"(acc[r][j]) : "l"(av[r]), "l"(b[j]));
            }
        }
        __syncthreads();
    }

    // epilogue (coalesced row-major stores)
    float bv[8];
#pragma unroll
    for (int i = 0; i < 8; i++) bv[i] = bias[n0 + tx * 8 + i];
#pragma unroll
    for (int r = 0; r < 8; r++) {
        int m = m0 + ty * 8 + r;
        float v[8];
#pragma unroll
        for (int j = 0; j < 4; j++) {
            float lo, hi;
            asm("mov.b64 {%0, %1}, %2;" : "=f"(lo), "=f"(hi) : "l"(acc[r][j]));
            v[j * 2]     = lo + bv[j * 2];
            v[j * 2 + 1] = hi + bv[j * 2 + 1];
        }
        *reinterpret_cast<float4*>(&C[(size_t)m * N + n0 + tx * 8])
            = make_float4(v[0], v[1], v[2], v[3]);
        *reinterpret_cast<float4*>(&C[(size_t)m * N + n0 + tx * 8 + 4])
            = make_float4(v[4], v[5], v[6], v[7]);
    }
}

// ---------------- assemble proposals + scores ----------------
__global__ void k_assemble(const float* __restrict__ anchd, float* __restrict__ out) {
    int row = blockIdx.x;            // b*42+e
    int b = row / NEDGE, e = row % NEDGE;
    float* prop   = out + (size_t)b * NPROP * NPRED;
    float* scores = out + (size_t)NB * NPROP * NPRED + (size_t)NB * NPROP + (size_t)b * NPROP;
    const float* rc = g_rc + (size_t)row * NPAD;
    for (int l = threadIdx.x; l < NANG * NPRED; l += blockDim.x) {
        int a = l / NPRED, q = l % NPRED;
        int p = e * NANG + a;
        float v;
        if (q < 2)      v = rc[NREG + a * 2 + q];
        else if (q < 4) v = anchd[(size_t)p * NPRED + q];
        else            v = anchd[(size_t)p * NPRED + q] + rc[a * 73 + (q - 4)];
        prop[(size_t)p * NPRED + q] = v;
    }
    if (threadIdx.x < NANG) {
        int a = threadIdx.x;
        int p = e * NANG + a;
        float l0 = rc[NREG + a * 2];
        float l1 = rc[NREG + a * 2 + 1];
        scores[p] = 1.0f / (1.0f + expf(l0 - l1));
    }
}

// ---------------- NMS: stable descending argsort + sorted gather ----------------
__global__ void k_sort(const float* __restrict__ out) {
    int b = blockIdx.x;
    __shared__ float s[NPROP];
    const float* scores = out + (size_t)NB * NPROP * NPRED + (size_t)NB * NPROP + (size_t)b * NPROP;
    const float* prop   = out + (size_t)b * NPROP * NPRED;
    for (int i = threadIdx.x; i < NPROP; i += blockDim.x) s[i] = scores[i];
    __syncthreads();
    for (int i = threadIdx.x; i < NPROP; i += blockDim.x) {
        float si = s[i];
        int r = 0;
        for (int j = 0; j < NPROP; j++) {
            float sj = s[j];
            r += (sj > si) || (sj == si && j < i);
        }
        int base = b * NPROP + r;
        g_order[base] = i;
        float p2 = prop[(size_t)i * NPRED + 2];
        float p4 = prop[(size_t)i * NPRED + 4];
        float st = fminf(fmaxf(rintf(p2 * NSTRIPSF), 0.0f), NSTRIPSF);
        float en = fminf(fmaxf(st + p4 - 1.0f, 0.0f), NSTRIPSF);
        g_sstart[base] = st;
        g_send[base]   = en;
        float* dst = g_sxs + (size_t)base * NOFF;
        const float* src = prop + (size_t)i * NPRED + 5;
        for (int k = 0; k < NOFF; k++) dst[k] = src[k];
    }
}

// ---------------- NMS: pairwise suppression bitmatrix ----------------
__global__ void k_pairs() {
    int b    = blockIdx.y;
    int warp = threadIdx.x >> 5;
    int lane = threadIdx.x & 31;
    int i    = blockIdx.x * 8 + warp;
    if (i >= NPROP) return;
    int base = b * NPROP;
    float si = g_sstart[base + i], ei = g_send[base + i];
    const float* xi = g_sxs + (size_t)(base + i) * NOFF;
    for (int jw = 0; jw < NWORDS; jw++) {
        int j = jw * 32 + lane;
        bool sup = false;
        if (j < NPROP) {
            float s  = fmaxf(si, g_sstart[base + j]);
            float e  = fminf(ei, g_send[base + j]);
            float cnt = e - s + 1.0f;
            if (cnt > 0.0f) {
                const float* xj = g_sxs + (size_t)(base + j) * NOFF;
                int k0 = (int)s;
                int k1 = (int)floorf(e);
                float sum = 0.0f;
                for (int k = k0; k <= k1; k++) sum += fabsf(xi[k] - xj[k]);
                sup = (sum / fmaxf(cnt, 1.0f)) < NMS_T;
            }
        }
        unsigned m = __ballot_sync(0xFFFFFFFFu, sup);
        if (lane == 0) g_sup[(size_t)(base + i) * NWORDS + jw] = m;
    }
}

// ---------------- NMS: sequential scan, smem-staged (256 thr: warp0 scans, rest load) ----------------
__global__ __launch_bounds__(256) void k_scan(float* __restrict__ out) {
    int b = blockIdx.x;
    __shared__ unsigned ssup[2][NCHUNK][NWORDS + 1];
    __shared__ int      sorder[NPROP];
    __shared__ float    skeep [NPROP];
    int t = threadIdx.x, lane = t & 31, warp = t >> 5;
    int base = b * NPROP;
    const unsigned* gs = g_sup + (size_t)base * NWORDS;

    for (int i = t; i < NPROP; i += 256) sorder[i] = g_order[base + i];
    // chunk 0
    for (int x = t; x < NCHUNK * NWORDS; x += 256)
        ssup[0][x / NWORDS][x % NWORDS] = gs[x];
    __syncthreads();

    unsigned my = 0;   // warp0: lane w (< NWORDS) owns suppressed-bit word w
    for (int c = 0; c < NCHUNKS; c++) {
        if (warp != 0) {
            if (c + 1 < NCHUNKS) {
                int i0 = (c + 1) * NCHUNK;
                int cnt = min(NCHUNK, NPROP - i0) * NWORDS;
                int tt = t - 32;
                for (int x = tt; x < cnt; x += 224)
                    ssup[(c + 1) & 1][x / NWORDS][x % NWORDS] = gs[(size_t)i0 * NWORDS + x];
            }
        } else {
            int i1 = min(NPROP, (c + 1) * NCHUNK);
            int lw = (lane < NWORDS) ? lane : 0;
            for (int i = c * NCHUNK; i < i1; i++) {
                unsigned row = ssup[c & 1][i - c * NCHUNK][lw];
                int wi = i >> 5, bit = i & 31;
                unsigned wsup = __shfl_sync(0xFFFFFFFFu, my, wi);
                bool kept = ((wsup >> bit) & 1u) == 0u;
                if (kept) {
                    unsigned m;
                    if (lane > wi)       m = 0xFFFFFFFFu;
                    else if (lane == wi) m = (bit == 31) ? 0u : (0xFFFFFFFFu << (bit + 1));
                    else                 m = 0u;
                    my |= row & m;
                }
                if (lane == 0) skeep[sorder[i]] = kept ? 1.0f : 0.0f;
            }
        }
        __syncthreads();
    }
    float* keep = out + (size_t)NB * NPROP * NPRED + (size_t)b * NPROP;
    for (int i = t; i < NPROP; i += 256) keep[i] = skeep[i];
}

// ---------------- launcher ----------------
extern "C" void kernel_launch(void* const* d_in, const int* in_sizes, int n_in,
                              void* d_out, int out_size) {
    const float* feat   = (const float*)d_in[0];
    const float* W_conv = (const float*)d_in[1];
    const float* b_conv = (const float*)d_in[2];
    const float* W_cls  = (const float*)d_in[3];
    const float* b_cls  = (const float*)d_in[4];
    const float* W_reg  = (const float*)d_in[5];
    const float* b_reg  = (const float*)d_in[6];
    const float* anchd  = (const float*)d_in[8];
    float* out = (float*)d_out;

    void *p_featE, *p_conv, *p_rc, *p_Wc, *p_bc;
    cudaGetSymbolAddress(&p_featE, g_featE);
    cudaGetSymbolAddress(&p_conv,  g_conv);
    cudaGetSymbolAddress(&p_rc,    g_rc);
    cudaGetSymbolAddress(&p_Wc,    g_Wc);
    cudaGetSymbolAddress(&p_bc,    g_bc);

    k_packW<<<(NPAD * (KCONV / 4) + 255) / 256, 256>>>(W_reg, b_reg, W_cls, b_cls);
    k_gather<<<(KBACK * MROWS + 255) / 256, 256>>>(feat);
    k_gemm<<<dim3(KCONV / 128, MROWS / 64), 128>>>(
        (const float*)p_featE, W_conv, b_conv, (float*)p_conv, KBACK, KCONV);
    k_gemm<<<dim3(NPAD / 128, MROWS / 64), 128>>>(
        (const float*)p_conv, (const float*)p_Wc, (const float*)p_bc,
        (float*)p_rc, KCONV, NPAD);
    k_assemble<<<MROWS, 256>>>(anchd, out);
    k_sort<<<NB, 256>>>(out);
    k_pairs<<<dim3((NPROP + 7) / 8, NB), 256>>>();
    k_scan<<<NB, 256>>>(out);
}

// round 5
// speedup vs baseline: 1.9957x; 1.2269x over previous
#include <cuda_runtime.h>
#include <math.h>

// ---------------- problem constants ----------------
#define NB      32
#define FH      11
#define FW      20
#define NEDGE   42
#define NANG    17
#define NPRED   77
#define NPROP   714
#define NOFF    72
#define KBACK   512
#define KCONV   1024
#define NREG    1241
#define NCLS    34
#define NPAD    1280        // NREG + NCLS padded to 128 multiple
#define MROWS   1344        // NB * NEDGE
#define NWORDS  23
#define NSTRIPSF 71.0f
#define NMS_T   15.0f
#define NCHUNK  128
#define NCHUNKS 6
#define KSPLIT  4

// ---------------- scratch ----------------
__device__ float    g_featE [MROWS * KBACK];          // [m][c] row-major
__device__ float    g_conv  [MROWS * KCONV];          // [m][n] row-major
__device__ float    g_rc    [MROWS * NPAD];           // fused reg|cls output
__device__ float    g_Wc    [NPAD * KCONV];           // packed W_reg|W_cls
__device__ float    g_bc    [NPAD];
__device__ float    g_part  [KSPLIT * MROWS * NPAD];  // K-split partials
__device__ int      g_order [NB * NPROP];
__device__ float    g_sstart[NB * NPROP];
__device__ float    g_send  [NB * NPROP];
__device__ float    g_sxs   [NB * NPROP * NOFF];
__device__ unsigned g_sup   [NB * NPROP * NWORDS];

// ---------------- pack combined weights (reg | cls | zero pad) ----------------
__global__ void k_packW(const float* __restrict__ Wr, const float* __restrict__ br,
                        const float* __restrict__ Wc, const float* __restrict__ bc) {
    int i = blockIdx.x * blockDim.x + threadIdx.x;      // float4 index
    if (i < NPAD * (KCONV / 4)) {
        int row = i >> 8;
        int c4  = i & 255;
        float4 v = make_float4(0.f, 0.f, 0.f, 0.f);
        if (row < NREG)      v = *reinterpret_cast<const float4*>(&Wr[(size_t)row * KCONV + c4 * 4]);
        else if (row < NREG + NCLS)
                             v = *reinterpret_cast<const float4*>(&Wc[(size_t)(row - NREG) * KCONV + c4 * 4]);
        reinterpret_cast<float4*>(g_Wc)[i] = v;
    }
    if (i < NPAD) {
        float v = 0.f;
        if (i < NREG)             v = br[i];
        else if (i < NREG + NCLS) v = bc[i - NREG];
        g_bc[i] = v;
    }
}

// ---------------- gather edge features, row-major [m][c] ----------------
__global__ void k_gather(const float* __restrict__ feat) {
    int x = blockIdx.x * blockDim.x + threadIdx.x;
    if (x >= KBACK * MROWS) return;
    int c = x & (KBACK - 1);
    int m = x >> 9;
    int b = m / NEDGE, e = m % NEDGE;
    int h, w;
    if (e < FH)        { h = e;      w = 0;        }
    else if (e < 2*FH) { h = e - FH; w = FW - 1;   }
    else               { h = FH - 1; w = e - 2*FH; }
    g_featE[x] = feat[((size_t)(b * KBACK + c) * FH + h) * FW + w];
}

// ---------------- fp32 GEMM, fma.rn.f32x2, 64Mx128N tile, 8x8 microtile, K-split ----------------
// Cpart[z][m][n] = sum_{k in split z} A[m][k] * W[n][k]
// 128 threads; (K/KSPLIT) % 16 == 0, N % 128 == 0, M % 64 == 0.
__global__ __launch_bounds__(128, 3) void k_gemm(
    const float* __restrict__ A, const float* __restrict__ W,
    float* __restrict__ Cpart, int K, int N)
{
    __shared__ __align__(16) unsigned long long As2[2][16][66];   // [kk][m] dup (a,a) pairs
    __shared__ __align__(16) float              Bsf[2][16][4][34];// [kk][j][tx*2+e]
    const int m0 = blockIdx.y * 64;
    const int n0 = blockIdx.x * 128;
    const int t  = threadIdx.x;
    const int tx = t & 15, ty = t >> 4;
    const int kbase  = blockIdx.z * (K / KSPLIT);
    const int ntiles = (K / KSPLIT) >> 4;
    float* C = Cpart + (size_t)blockIdx.z * MROWS * N;

    float4 ra[2], rb[4];

    auto load_tile = [&](int k0) {
#pragma unroll
        for (int i = 0; i < 2; i++) {
            int idx = t + i * 128;
            int m = idx >> 2, kq = idx & 3;
            ra[i] = *reinterpret_cast<const float4*>(&A[(size_t)(m0 + m) * K + k0 + kq * 4]);
        }
#pragma unroll
        for (int i = 0; i < 4; i++) {
            int idx = t + i * 128;
            int n = idx >> 2, kw = idx & 3;
            rb[i] = *reinterpret_cast<const float4*>(&W[(size_t)(n0 + n) * K + k0 + kw * 4]);
        }
    };
    auto store_tile = [&](int buf) {
#pragma unroll
        for (int i = 0; i < 2; i++) {
            int idx = t + i * 128;
            int m = idx >> 2, kq = idx & 3;
            float v[4] = {ra[i].x, ra[i].y, ra[i].z, ra[i].w};
#pragma unroll
            for (int j = 0; j < 4; j++) {
                unsigned long long p;
                asm("mov.b64 %0, {%1, %1};" : "=l"(p) : "f"(v[j]));
                As2[buf][kq * 4 + j][m] = p;
            }
        }
#pragma unroll
        for (int i = 0; i < 4; i++) {
            int idx = t + i * 128;
            int n = idx >> 2, kw = idx & 3;
            int jj = (n >> 1) & 3, ee = (n >> 3) * 2 + (n & 1);
            float v[4] = {rb[i].x, rb[i].y, rb[i].z, rb[i].w};
#pragma unroll
            for (int q = 0; q < 4; q++)
                Bsf[buf][kw * 4 + q][jj][ee] = v[q];
        }
    };

    unsigned long long acc[8][4];
#pragma unroll
    for (int r = 0; r < 8; r++)
#pragma unroll
        for (int c = 0; c < 4; c++) acc[r][c] = 0ull;

    load_tile(kbase);
    store_tile(0);
    if (ntiles > 1) load_tile(kbase + 16);
    __syncthreads();

    for (int i = 0; i < ntiles; i++) {
        int buf = i & 1;
        if (i + 1 < ntiles) store_tile((i + 1) & 1);
        if (i + 2 < ntiles) load_tile(kbase + ((i + 2) << 4));
#pragma unroll
        for (int kk = 0; kk < 16; kk++) {
            ulonglong2 a01 = *reinterpret_cast<const ulonglong2*>(&As2[buf][kk][ty * 8 + 0]);
            ulonglong2 a23 = *reinterpret_cast<const ulonglong2*>(&As2[buf][kk][ty * 8 + 2]);
            ulonglong2 a45 = *reinterpret_cast<const ulonglong2*>(&As2[buf][kk][ty * 8 + 4]);
            ulonglong2 a67 = *reinterpret_cast<const ulonglong2*>(&As2[buf][kk][ty * 8 + 6]);
            unsigned long long b[4];
#pragma unroll
            for (int j = 0; j < 4; j++)
                b[j] = *reinterpret_cast<const unsigned long long*>(&Bsf[buf][kk][j][tx * 2]);
            unsigned long long av[8] = {a01.x, a01.y, a23.x, a23.y, a45.x, a45.y, a67.x, a67.y};
#pragma unroll
            for (int r = 0; r < 8; r++) {
#pragma unroll
                for (int j = 0; j < 4; j++)
                    asm("fma.rn.f32x2 %0, %1, %2, %0;" : "+l"(acc[r][j]) : "l"(av[r]), "l"(b[j]));
            }
        }
        __syncthreads();
    }

    // epilogue: raw partials (bias added in reduce)
#pragma unroll
    for (int r = 0; r < 8; r++) {
        int m = m0 + ty * 8 + r;
        float v[8];
#pragma unroll
        for (int j = 0; j < 4; j++) {
            float lo, hi;
            asm("mov.b64 {%0, %1}, %2;" : "=f"(lo), "=f"(hi) : "l"(acc[r][j]));
            v[j * 2]     = lo;
            v[j * 2 + 1] = hi;
        }
        *reinterpret_cast<float4*>(&C[(size_t)m * N + n0 + tx * 8])
            = make_float4(v[0], v[1], v[2], v[3]);
        *reinterpret_cast<float4*>(&C[(size_t)m * N + n0 + tx * 8 + 4])
            = make_float4(v[4], v[5], v[6], v[7]);
    }
}

// ---------------- reduce K-split partials + bias ----------------
__global__ void k_reduce(const float* __restrict__ part, const float* __restrict__ bias,
                         float* __restrict__ C, int N) {
    int i = blockIdx.x * blockDim.x + threadIdx.x;    // float4 index
    int total = MROWS * (N >> 2);
    if (i >= total) return;
    size_t stride = (size_t)MROWS * (N >> 2);
    const float4* p = reinterpret_cast<const float4*>(part);
    float4 a = p[i];
#pragma unroll
    for (int s = 1; s < KSPLIT; s++) {
        float4 b = p[s * stride + i];
        a.x += b.x; a.y += b.y; a.z += b.z; a.w += b.w;
    }
    int n = (i << 2) & (N - 1);    // N is power-of-two multiple? N=1024 yes, N=1280 no!
    n = (i % (N >> 2)) << 2;
    float4 bv = *reinterpret_cast<const float4*>(&bias[n]);
    a.x += bv.x; a.y += bv.y; a.z += bv.z; a.w += bv.w;
    reinterpret_cast<float4*>(C)[i] = a;
}

// ---------------- assemble proposals + scores ----------------
__global__ void k_assemble(const float* __restrict__ anchd, float* __restrict__ out) {
    int row = blockIdx.x;            // b*42+e
    int b = row / NEDGE, e = row % NEDGE;
    float* prop   = out + (size_t)b * NPROP * NPRED;
    float* scores = out + (size_t)NB * NPROP * NPRED + (size_t)NB * NPROP + (size_t)b * NPROP;
    const float* rc = g_rc + (size_t)row * NPAD;
    for (int l = threadIdx.x; l < NANG * NPRED; l += blockDim.x) {
        int a = l / NPRED, q = l % NPRED;
        int p = e * NANG + a;
        float v;
        if (q < 2)      v = rc[NREG + a * 2 + q];
        else if (q < 4) v = anchd[(size_t)p * NPRED + q];
        else            v = anchd[(size_t)p * NPRED + q] + rc[a * 73 + (q - 4)];
        prop[(size_t)p * NPRED + q] = v;
    }
    if (threadIdx.x < NANG) {
        int a = threadIdx.x;
        int p = e * NANG + a;
        float l0 = rc[NREG + a * 2];
        float l1 = rc[NREG + a * 2 + 1];
        scores[p] = 1.0f / (1.0f + expf(l0 - l1));
    }
}

// ---------------- NMS: stable descending argsort + sorted gather ----------------
__global__ void k_sort(const float* __restrict__ out) {
    int b = blockIdx.x;
    __shared__ float s[NPROP];
    const float* scores = out + (size_t)NB * NPROP * NPRED + (size_t)NB * NPROP + (size_t)b * NPROP;
    const float* prop   = out + (size_t)b * NPROP * NPRED;
    for (int i = threadIdx.x; i < NPROP; i += blockDim.x) s[i] = scores[i];
    __syncthreads();
    for (int i = threadIdx.x; i < NPROP; i += blockDim.x) {
        float si = s[i];
        int r = 0;
        for (int j = 0; j < NPROP; j++) {
            float sj = s[j];
            r += (sj > si) || (sj == si && j < i);
        }
        int base = b * NPROP + r;
        g_order[base] = i;
        float p2 = prop[(size_t)i * NPRED + 2];
        float p4 = prop[(size_t)i * NPRED + 4];
        float st = fminf(fmaxf(rintf(p2 * NSTRIPSF), 0.0f), NSTRIPSF);
        float en = fminf(fmaxf(st + p4 - 1.0f, 0.0f), NSTRIPSF);
        g_sstart[base] = st;
        g_send[base]   = en;
        float* dst = g_sxs + (size_t)base * NOFF;
        const float* src = prop + (size_t)i * NPRED + 5;
        for (int k = 0; k < NOFF; k++) dst[k] = src[k];
    }
}

// ---------------- NMS: pairwise suppression bitmatrix ----------------
__global__ void k_pairs() {
    int b    = blockIdx.y;
    int warp = threadIdx.x >> 5;
    int lane = threadIdx.x & 31;
    int i    = blockIdx.x * 8 + warp;
    if (i >= NPROP) return;
    int base = b * NPROP;
    float si = g_sstart[base + i], ei = g_send[base + i];
    const float* xi = g_sxs + (size_t)(base + i) * NOFF;
    for (int jw = 0; jw < NWORDS; jw++) {
        int j = jw * 32 + lane;
        bool sup = false;
        if (j < NPROP) {
            float s  = fmaxf(si, g_sstart[base + j]);
            float e  = fminf(ei, g_send[base + j]);
            float cnt = e - s + 1.0f;
            if (cnt > 0.0f) {
                const float* xj = g_sxs + (size_t)(base + j) * NOFF;
                int k0 = (int)s;
                int k1 = (int)floorf(e);
                float sum = 0.0f;
                for (int k = k0; k <= k1; k++) sum += fabsf(xi[k] - xj[k]);
                sup = (sum / fmaxf(cnt, 1.0f)) < NMS_T;
            }
        }
        unsigned m = __ballot_sync(0xFFFFFFFFu, sup);
        if (lane == 0) g_sup[(size_t)(base + i) * NWORDS + jw] = m;
    }
}

// ---------------- NMS: sequential scan, smem-staged ----------------
__global__ __launch_bounds__(256) void k_scan(float* __restrict__ out) {
    int b = blockIdx.x;
    __shared__ unsigned ssup[2][NCHUNK][NWORDS + 1];
    __shared__ int      sorder[NPROP];
    __shared__ float    skeep [NPROP];
    int t = threadIdx.x, lane = t & 31, warp = t >> 5;
    int base = b * NPROP;
    const unsigned* gs = g_sup + (size_t)base * NWORDS;

    for (int i = t; i < NPROP; i += 256) sorder[i] = g_order[base + i];
    for (int x = t; x < NCHUNK * NWORDS; x += 256)
        ssup[0][x / NWORDS][x % NWORDS] = gs[x];
    __syncthreads();

    unsigned my = 0;
    for (int c = 0; c < NCHUNKS; c++) {
        if (warp != 0) {
            if (c + 1 < NCHUNKS) {
                int i0 = (c + 1) * NCHUNK;
                int cnt = min(NCHUNK, NPROP - i0) * NWORDS;
                int tt = t - 32;
                for (int x = tt; x < cnt; x += 224)
                    ssup[(c + 1) & 1][x / NWORDS][x % NWORDS] = gs[(size_t)i0 * NWORDS + x];
            }
        } else {
            int i1 = min(NPROP, (c + 1) * NCHUNK);
            int lw = (lane < NWORDS) ? lane : 0;
            for (int i = c * NCHUNK; i < i1; i++) {
                unsigned row = ssup[c & 1][i - c * NCHUNK][lw];
                int wi = i >> 5, bit = i & 31;
                unsigned wsup = __shfl_sync(0xFFFFFFFFu, my, wi);
                bool kept = ((wsup >> bit) & 1u) == 0u;
                if (kept) {
                    unsigned m;
                    if (lane > wi)       m = 0xFFFFFFFFu;
                    else if (lane == wi) m = (bit == 31) ? 0u : (0xFFFFFFFFu << (bit + 1));
                    else                 m = 0u;
                    my |= row & m;
                }
                if (lane == 0) skeep[sorder[i]] = kept ? 1.0f : 0.0f;
            }
        }
        __syncthreads();
    }
    float* keep = out + (size_t)NB * NPROP * NPRED + (size_t)b * NPROP;
    for (int i = t; i < NPROP; i += 256) keep[i] = skeep[i];
}

// ---------------- launcher ----------------
extern "C" void kernel_launch(void* const* d_in, const int* in_sizes, int n_in,
                              void* d_out, int out_size) {
    const float* feat   = (const float*)d_in[0];
    const float* W_conv = (const float*)d_in[1];
    const float* b_conv = (const float*)d_in[2];
    const float* W_cls  = (const float*)d_in[3];
    const float* b_cls  = (const float*)d_in[4];
    const float* W_reg  = (const float*)d_in[5];
    const float* b_reg  = (const float*)d_in[6];
    const float* anchd  = (const float*)d_in[8];
    float* out = (float*)d_out;

    void *p_featE, *p_conv, *p_rc, *p_Wc, *p_bc, *p_part;
    cudaGetSymbolAddress(&p_featE, g_featE);
    cudaGetSymbolAddress(&p_conv,  g_conv);
    cudaGetSymbolAddress(&p_rc,    g_rc);
    cudaGetSymbolAddress(&p_Wc,    g_Wc);
    cudaGetSymbolAddress(&p_bc,    g_bc);
    cudaGetSymbolAddress(&p_part,  g_part);

    k_packW<<<(NPAD * (KCONV / 4) + 255) / 256, 256>>>(W_reg, b_reg, W_cls, b_cls);
    k_gather<<<(KBACK * MROWS + 255) / 256, 256>>>(feat);

    // GEMM1: featE(1344x512) @ W_conv(1024x512)^T -> conv(1344x1024)
    k_gemm<<<dim3(KCONV / 128, MROWS / 64, KSPLIT), 128>>>(
        (const float*)p_featE, W_conv, (float*)p_part, KBACK, KCONV);
    k_reduce<<<(MROWS * (KCONV / 4) + 255) / 256, 256>>>(
        (const float*)p_part, b_conv, (float*)p_conv, KCONV);

    // GEMM2: conv(1344x1024) @ Wc(1280x1024)^T -> rc(1344x1280)
    k_gemm<<<dim3(NPAD / 128, MROWS / 64, KSPLIT), 128>>>(
        (const float*)p_conv, (const float*)p_Wc, (float*)p_part, KCONV, NPAD);
    k_reduce<<<(MROWS * (NPAD / 4) + 255) / 256, 256>>>(
        (const float*)p_part, (const float*)p_bc, (float*)p_rc, NPAD);

    k_assemble<<<MROWS, 256>>>(anchd, out);
    k_sort<<<NB, 256>>>(out);
    k_pairs<<<dim3((NPROP + 7) / 8, NB), 256>>>();
    k_scan<<<NB, 256>>>(out);
}

// round 7
// speedup vs baseline: 2.1427x; 1.0736x over previous
#include <cuda_runtime.h>
#include <math.h>
#include <stdint.h>

// ---------------- problem constants ----------------
#define NB      32
#define FH      11
#define FW      20
#define NEDGE   42
#define NANG    17
#define NPRED   77
#define NPROP   714
#define NOFF    72
#define KBACK   512
#define KCONV   1024
#define NREG    1241
#define NCLS    34
#define NPAD    1280        // NREG + NCLS padded to 128
#define MROWS   1344        // NB * NEDGE
#define MPAD    1408        // 11 * 128
#define NWORDS  23
#define NSTRIPSF 71.0f
#define NMS_T   15.0f
#define NCHUNK  128
#define NCHUNKS 6
#define KC      16          // K per pipeline chunk (2 k8 mma steps)
#define SA      20          // smem row stride (floats): pad for banks + f4 align

// ---------------- scratch ----------------
__device__ float    g_featE [MPAD * KBACK];     // edge features (pad rows stay 0)
__device__ float    g_conv  [MPAD * KCONV];     // gemm1 output
__device__ float    g_Wc    [NPAD * KCONV];     // packed W_reg|W_cls
__device__ float    g_bc    [NPAD];
__device__ float    g_rc    [MPAD * NPAD];      // fused reg|cls output
__device__ int      g_order [NB * NPROP];
__device__ float    g_sstart[NB * NPROP];
__device__ float    g_send  [NB * NPROP];
__device__ float    g_sxs   [NB * NPROP * NOFF];
__device__ unsigned g_sup   [NB * NPROP * NWORDS];

// ---------------- helpers ----------------
__device__ __forceinline__ void split2(float x, uint32_t& h, uint32_t& l) {
    asm("cvt.rna.tf32.f32 %0, %1;" : "=r"(h) : "f"(x));
    float r = x - __uint_as_float(h);
    asm("cvt.rna.tf32.f32 %0, %1;" : "=r"(l) : "f"(r));
}
#define MMA_TF32(d, a, b)                                                        \
    asm volatile("mma.sync.aligned.m16n8k8.row.col.f32.tf32.tf32.f32 "           \
        "{%0,%1,%2,%3}, {%4,%5,%6,%7}, {%8,%9}, {%0,%1,%2,%3};"                  \
        : "+f"((d)[0]), "+f"((d)[1]), "+f"((d)[2]), "+f"((d)[3])                 \
        : "r"((a)[0]), "r"((a)[1]), "r"((a)[2]), "r"((a)[3]),                    \
          "r"((b)[0]), "r"((b)[1]))

// ---------------- pack combined weights (reg | cls | zero pad) ----------------
__global__ void k_packW(const float* __restrict__ Wr, const float* __restrict__ br,
                        const float* __restrict__ Wc, const float* __restrict__ bc) {
    int i = blockIdx.x * blockDim.x + threadIdx.x;      // float4 index
    if (i < NPAD * (KCONV / 4)) {
        int row = i >> 8, c4 = i & 255;
        float4 v = make_float4(0.f, 0.f, 0.f, 0.f);
        if (row < NREG)      v = *reinterpret_cast<const float4*>(&Wr[(size_t)row * KCONV + c4 * 4]);
        else if (row < NREG + NCLS)
                             v = *reinterpret_cast<const float4*>(&Wc[(size_t)(row - NREG) * KCONV + c4 * 4]);
        reinterpret_cast<float4*>(g_Wc)[i] = v;
    }
    if (i < NPAD) {
        float v = 0.f;
        if (i < NREG)             v = br[i];
        else if (i < NREG + NCLS) v = bc[i - NREG];
        g_bc[i] = v;
    }
}

// ---------------- gather edge features, row-major [m][c] ----------------
__global__ void k_gather(const float* __restrict__ feat) {
    int x = blockIdx.x * blockDim.x + threadIdx.x;
    if (x >= KBACK * MROWS) return;
    int c = x & (KBACK - 1);
    int m = x >> 9;
    int b = m / NEDGE, e = m % NEDGE;
    int h, w;
    if (e < FH)        { h = e;      w = 0;        }
    else if (e < 2*FH) { h = e - FH; w = FW - 1;   }
    else               { h = FH - 1; w = e - 2*FH; }
    g_featE[x] = feat[((size_t)(b * KBACK + c) * FH + h) * FW + w];
}

// ---------------- tf32 mma.sync GEMM with 3xTF32 decomposition ----------------
// C[m][n] = sum_k A[m][k] * W[n][k] + bias[n]
// CTA tile 128x128, 8 warps (warp tile 32x64), KC=16 double-buffered smem.
// hi/lo tf32 split done on the fly at smem-store time.
__global__ __launch_bounds__(256, 1) void k_gemm_mma(
    const float* __restrict__ A, const float* __restrict__ W,
    const float* __restrict__ bias, float* __restrict__ C,
    int K, int N)
{
    extern __shared__ float smf[];
    // per stage: Ah[128*SA], Al, Bh, Bl  -> 4*2560 floats; 2 stages
    const int m0 = blockIdx.y * 128, n0 = blockIdx.x * 128;
    const int t = threadIdx.x, w = t >> 5, lane = t & 31;
    const int g = lane >> 2, c = lane & 3;
    const int wm = w & 3, wn = w >> 2;          // warp tile: rows wm*32, cols wn*64

    // global-load indexing: per matrix, 512 float4 / 256 thr = 2 each
    const int rA0 = t >> 2,          c4A0 = t & 3;
    const int rA1 = (t + 256) >> 2,  c4A1 = (t + 256) & 3;

    float4 ra[2], rb[2];
    auto load_regs = [&](int kb) {
        ra[0] = *reinterpret_cast<const float4*>(&A[(size_t)(m0 + rA0) * K + kb + c4A0 * 4]);
        ra[1] = *reinterpret_cast<const float4*>(&A[(size_t)(m0 + rA1) * K + kb + c4A1 * 4]);
        rb[0] = *reinterpret_cast<const float4*>(&W[(size_t)(n0 + rA0) * K + kb + c4A0 * 4]);
        rb[1] = *reinterpret_cast<const float4*>(&W[(size_t)(n0 + rA1) * K + kb + c4A1 * 4]);
    };
    auto store_stage = [&](int st) {
        float* Ah = smf + st * 10240;
        float* Al = Ah + 2560;
        float* Bh = Al + 2560;
        float* Bl = Bh + 2560;
#pragma unroll
        for (int i = 0; i < 2; i++) {
            int r  = i ? rA1 : rA0;
            int c4 = i ? c4A1 : c4A0;
            float va[4] = {ra[i].x, ra[i].y, ra[i].z, ra[i].w};
            float vb[4] = {rb[i].x, rb[i].y, rb[i].z, rb[i].w};
            uint32_t ah[4], al[4], bh[4], bl[4];
#pragma unroll
            for (int j = 0; j < 4; j++) { split2(va[j], ah[j], al[j]); split2(vb[j], bh[j], bl[j]); }
            int off = r * SA + c4 * 4;
            *reinterpret_cast<uint4*>(&Ah[off]) = make_uint4(ah[0], ah[1], ah[2], ah[3]);
            *reinterpret_cast<uint4*>(&Al[off]) = make_uint4(al[0], al[1], al[2], al[3]);
            *reinterpret_cast<uint4*>(&Bh[off]) = make_uint4(bh[0], bh[1], bh[2], bh[3]);
            *reinterpret_cast<uint4*>(&Bl[off]) = make_uint4(bl[0], bl[1], bl[2], bl[3]);
        }
    };

    float acc[2][8][4];
#pragma unroll
    for (int mt = 0; mt < 2; mt++)
#pragma unroll
        for (int nt = 0; nt < 8; nt++)
#pragma unroll
            for (int e = 0; e < 4; e++) acc[mt][nt][e] = 0.f;

    const int nch = K / KC;
    load_regs(0);
    store_stage(0);
    __syncthreads();

    for (int ch = 0; ch < nch; ch++) {
        int st = ch & 1;
        if (ch + 1 < nch) load_regs((ch + 1) * KC);
        const float* Ah = smf + st * 10240;
        const float* Al = Ah + 2560;
        const float* Bh = Al + 2560;
        const float* Bl = Bh + 2560;
#pragma unroll
        for (int kb = 0; kb < KC; kb += 8) {
            uint32_t ah[2][4], al[2][4], bh[8][2], bl[8][2];
#pragma unroll
            for (int mt = 0; mt < 2; mt++) {
                int mr = (wm * 32 + mt * 16 + g) * SA + kb + c;
                ah[mt][0] = __float_as_uint(Ah[mr]);
                ah[mt][1] = __float_as_uint(Ah[mr + 8 * SA]);
                ah[mt][2] = __float_as_uint(Ah[mr + 4]);
                ah[mt][3] = __float_as_uint(Ah[mr + 8 * SA + 4]);
                al[mt][0] = __float_as_uint(Al[mr]);
                al[mt][1] = __float_as_uint(Al[mr + 8 * SA]);
                al[mt][2] = __float_as_uint(Al[mr + 4]);
                al[mt][3] = __float_as_uint(Al[mr + 8 * SA + 4]);
            }
#pragma unroll
            for (int nt = 0; nt < 8; nt++) {
                int nr = (wn * 64 + nt * 8 + g) * SA + kb + c;
                bh[nt][0] = __float_as_uint(Bh[nr]);
                bh[nt][1] = __float_as_uint(Bh[nr + 4]);
                bl[nt][0] = __float_as_uint(Bl[nr]);
                bl[nt][1] = __float_as_uint(Bl[nr + 4]);
            }
#pragma unroll
            for (int mt = 0; mt < 2; mt++)
#pragma unroll
                for (int nt = 0; nt < 8; nt++) {
                    MMA_TF32(acc[mt][nt], ah[mt], bh[nt]);
                    MMA_TF32(acc[mt][nt], ah[mt], bl[nt]);
                    MMA_TF32(acc[mt][nt], al[mt], bh[nt]);
                }
        }
        if (ch + 1 < nch) store_stage((ch + 1) & 1);
        __syncthreads();
    }

    // epilogue
#pragma unroll
    for (int mt = 0; mt < 2; mt++) {
        int row0 = m0 + wm * 32 + mt * 16 + g;
#pragma unroll
        for (int nt = 0; nt < 8; nt++) {
            int col = n0 + wn * 64 + nt * 8 + 2 * c;
            float b0 = bias[col], b1 = bias[col + 1];
            *reinterpret_cast<float2*>(&C[(size_t)row0 * N + col])
                = make_float2(acc[mt][nt][0] + b0, acc[mt][nt][1] + b1);
            *reinterpret_cast<float2*>(&C[(size_t)(row0 + 8) * N + col])
                = make_float2(acc[mt][nt][2] + b0, acc[mt][nt][3] + b1);
        }
    }
}

// ---------------- assemble proposals + scores ----------------
__global__ void k_assemble(const float* __restrict__ anchd, float* __restrict__ out) {
    int row = blockIdx.x;            // b*42+e
    int b = row / NEDGE, e = row % NEDGE;
    float* prop   = out + (size_t)b * NPROP * NPRED;
    float* scores = out + (size_t)NB * NPROP * NPRED + (size_t)NB * NPROP + (size_t)b * NPROP;
    const float* rc = g_rc + (size_t)row * NPAD;
    for (int l = threadIdx.x; l < NANG * NPRED; l += blockDim.x) {
        int a = l / NPRED, q = l % NPRED;
        int p = e * NANG + a;
        float v;
        if (q < 2)      v = rc[NREG + a * 2 + q];
        else if (q < 4) v = anchd[(size_t)p * NPRED + q];
        else            v = anchd[(size_t)p * NPRED + q] + rc[a * 73 + (q - 4)];
        prop[(size_t)p * NPRED + q] = v;
    }
    if (threadIdx.x < NANG) {
        int a = threadIdx.x;
        int p = e * NANG + a;
        float l0 = rc[NREG + a * 2];
        float l1 = rc[NREG + a * 2 + 1];
        scores[p] = 1.0f / (1.0f + expf(l0 - l1));
    }
}

// ---------------- NMS: stable descending argsort + sorted gather ----------------
__global__ void k_sort(const float* __restrict__ out) {
    int b = blockIdx.x;
    __shared__ float s[NPROP];
    const float* scores = out + (size_t)NB * NPROP * NPRED + (size_t)NB * NPROP + (size_t)b * NPROP;
    const float* prop   = out + (size_t)b * NPROP * NPRED;
    for (int i = threadIdx.x; i < NPROP; i += blockDim.x) s[i] = scores[i];
    __syncthreads();
    for (int i = threadIdx.x; i < NPROP; i += blockDim.x) {
        float si = s[i];
        int r = 0;
        for (int j = 0; j < NPROP; j++) {
            float sj = s[j];
            r += (sj > si) || (sj == si && j < i);
        }
        int base = b * NPROP + r;
        g_order[base] = i;
        float p2 = prop[(size_t)i * NPRED + 2];
        float p4 = prop[(size_t)i * NPRED + 4];
        float st = fminf(fmaxf(rintf(p2 * NSTRIPSF), 0.0f), NSTRIPSF);
        float en = fminf(fmaxf(st + p4 - 1.0f, 0.0f), NSTRIPSF);
        g_sstart[base] = st;
        g_send[base]   = en;
        float* dst = g_sxs + (size_t)base * NOFF;
        const float* src = prop + (size_t)i * NPRED + 5;
        for (int k = 0; k < NOFF; k++) dst[k] = src[k];
    }
}

// ---------------- NMS: pairwise suppression bitmatrix ----------------
__global__ void k_pairs() {
    int b    = blockIdx.y;
    int warp = threadIdx.x >> 5;
    int lane = threadIdx.x & 31;
    int i    = blockIdx.x * 8 + warp;
    if (i >= NPROP) return;
    int base = b * NPROP;
    float si = g_sstart[base + i], ei = g_send[base + i];
    const float* xi = g_sxs + (size_t)(base + i) * NOFF;
    for (int jw = 0; jw < NWORDS; jw++) {
        int j = jw * 32 + lane;
        bool sup = false;
        if (j < NPROP) {
            float s  = fmaxf(si, g_sstart[base + j]);
            float e  = fminf(ei, g_send[base + j]);
            float cnt = e - s + 1.0f;
            if (cnt > 0.0f) {
                const float* xj = g_sxs + (size_t)(base + j) * NOFF;
                int k0 = (int)s;
                int k1 = (int)floorf(e);
                float sum = 0.0f;
                for (int k = k0; k <= k1; k++) sum += fabsf(xi[k] - xj[k]);
                sup = (sum / fmaxf(cnt, 1.0f)) < NMS_T;
            }
        }
        unsigned m = __ballot_sync(0xFFFFFFFFu, sup);
        if (lane == 0) g_sup[(size_t)(base + i) * NWORDS + jw] = m;
    }
}

// ---------------- NMS: sequential scan, smem-staged ----------------
__global__ __launch_bounds__(256) void k_scan(float* __restrict__ out) {
    int b = blockIdx.x;
    __shared__ unsigned ssup[2][NCHUNK][NWORDS + 1];
    __shared__ int      sorder[NPROP];
    __shared__ float    skeep [NPROP];
    int t = threadIdx.x, lane = t & 31, warp = t >> 5;
    int base = b * NPROP;
    const unsigned* gs = g_sup + (size_t)base * NWORDS;

    for (int i = t; i < NPROP; i += 256) sorder[i] = g_order[base + i];
    for (int x = t; x < NCHUNK * NWORDS; x += 256)
        ssup[0][x / NWORDS][x % NWORDS] = gs[x];
    __syncthreads();

    unsigned my = 0;
    for (int c = 0; c < NCHUNKS; c++) {
        if (warp != 0) {
            if (c + 1 < NCHUNKS) {
                int i0 = (c + 1) * NCHUNK;
                int cnt = min(NCHUNK, NPROP - i0) * NWORDS;
                int tt = t - 32;
                for (int x = tt; x < cnt; x += 224)
                    ssup[(c + 1) & 1][x / NWORDS][x % NWORDS] = gs[(size_t)i0 * NWORDS + x];
            }
        } else {
            int i1 = min(NPROP, (c + 1) * NCHUNK);
            int lw = (lane < NWORDS) ? lane : 0;
            for (int i = c * NCHUNK; i < i1; i++) {
                unsigned row = ssup[c & 1][i - c * NCHUNK][lw];
                int wi = i >> 5, bit = i & 31;
                unsigned wsup = __shfl_sync(0xFFFFFFFFu, my, wi);
                bool kept = ((wsup >> bit) & 1u) == 0u;
                if (kept) {
                    unsigned m;
                    if (lane > wi)       m = 0xFFFFFFFFu;
                    else if (lane == wi) m = (bit == 31) ? 0u : (0xFFFFFFFFu << (bit + 1));
                    else                 m = 0u;
                    my |= row & m;
                }
                if (lane == 0) skeep[sorder[i]] = kept ? 1.0f : 0.0f;
            }
        }
        __syncthreads();
    }
    float* keep = out + (size_t)NB * NPROP * NPRED + (size_t)b * NPROP;
    for (int i = t; i < NPROP; i += 256) keep[i] = skeep[i];
}

// ---------------- launcher ----------------
#define GEMM_SMEM (2 * 4 * 128 * SA * 4)   // 81920 bytes

extern "C" void kernel_launch(void* const* d_in, const int* in_sizes, int n_in,
                              void* d_out, int out_size) {
    const float* feat   = (const float*)d_in[0];
    const float* W_conv = (const float*)d_in[1];
    const float* b_conv = (const float*)d_in[2];
    const float* W_cls  = (const float*)d_in[3];
    const float* b_cls  = (const float*)d_in[4];
    const float* W_reg  = (const float*)d_in[5];
    const float* b_reg  = (const float*)d_in[6];
    const float* anchd  = (const float*)d_in[8];
    float* out = (float*)d_out;

    void *pFE, *pC, *pWc, *pBc, *pRC;
    cudaGetSymbolAddress(&pFE, g_featE);
    cudaGetSymbolAddress(&pC,  g_conv);
    cudaGetSymbolAddress(&pWc, g_Wc);
    cudaGetSymbolAddress(&pBc, g_bc);
    cudaGetSymbolAddress(&pRC, g_rc);

    cudaFuncSetAttribute(k_gemm_mma, cudaFuncAttributeMaxDynamicSharedMemorySize, GEMM_SMEM);

    k_packW<<<(NPAD * (KCONV / 4) + 255) / 256, 256>>>(W_reg, b_reg, W_cls, b_cls);
    k_gather<<<(KBACK * MROWS + 255) / 256, 256>>>(feat);

    // GEMM1: featE(1408x512) @ W_conv(1024x512)^T -> conv(1408x1024)
    k_gemm_mma<<<dim3(KCONV / 128, MPAD / 128), 256, GEMM_SMEM>>>(
        (const float*)pFE, W_conv, b_conv, (float*)pC, KBACK, KCONV);

    // GEMM2: conv(1408x1024) @ Wc(1280x1024)^T -> rc(1408x1280)
    k_gemm_mma<<<dim3(NPAD / 128, MPAD / 128), 256, GEMM_SMEM>>>(
        (const float*)pC, (const float*)pWc, (const float*)pBc, (float*)pRC, KCONV, NPAD);

    k_assemble<<<MROWS, 256>>>(anchd, out);
    k_sort<<<NB, 256>>>(out);
    k_pairs<<<dim3((NPROP + 7) / 8, NB), 256>>>();
    k_scan<<<NB, 256>>>(out);
}